// round 14
// baseline (speedup 1.0000x reference)
#include <cuda_runtime.h>
#include <cstdint>

// BalancedLoss fused kernel, R14: R10 structure exactly (grid-stride 8KB
// chunks => collectively-sequential DRAM sweep, L2 prefetch, 40 warps/SM),
// single change: PF_D 2 -> 3.
// Per column c: A_c = sum (1-t)*softplus(x), B_c = sum t*(softplus(x)-x),
// P_c = sum t;  loss = sum_c (w0_c*A_c + w1_c*B_c) / (B*C).

#define CCOLS 512
#define C4    128        // float4 groups per row
#define NBLK  740        // 5 CTAs/SM
#define NTHR  256
#define CHUNK_F4 512     // float4 per tensor per chunk (8 KB)
#define PF_D  3          // prefetch distance in grid-strides
#define REPL  4          // accumulator replicas (atomic contention)

__device__ float g_accA[REPL][CCOLS];
__device__ float g_accB[REPL][CCOLS];
__device__ float g_accP[REPL][CCOLS];
__device__ unsigned int g_done;

__device__ __forceinline__ void prefetch_l2(const void* p, uint32_t bytes) {
    asm volatile("cp.async.bulk.prefetch.L2.global [%0], %1;"
                 :: "l"(p), "r"(bytes) : "memory");
}

__device__ __forceinline__ float softplus_f(float x) {
    return fmaxf(x, 0.0f) + __logf(1.0f + __expf(-fabsf(x)));
}

struct Acc {
    float a0, a1, a2, a3, b0, b1, b2, b3, p0, p1, p2, p3;
};

__device__ __forceinline__ void bl_acc(Acc& ac, const float4& x, const float4& t) {
    float s;
    s = softplus_f(x.x); ac.a0 += s - s*t.x; ac.b0 += (s - x.x)*t.x; ac.p0 += t.x;
    s = softplus_f(x.y); ac.a1 += s - s*t.y; ac.b1 += (s - x.y)*t.y; ac.p1 += t.y;
    s = softplus_f(x.z); ac.a2 += s - s*t.z; ac.b2 += (s - x.z)*t.z; ac.p2 += t.z;
    s = softplus_f(x.w); ac.a3 += s - s*t.w; ac.b3 += (s - x.w)*t.w; ac.p3 += t.w;
}

__global__ __launch_bounds__(NTHR, 5)
void bl_pf_kernel(const float4* __restrict__ pred,
                  const float4* __restrict__ targ,
                  const float* __restrict__ pos_prop,
                  float* __restrict__ out,
                  int Bn) {
    const int tid  = threadIdx.x;
    const int grid = gridDim.x;
    const int total_f4 = Bn * C4;
    const int nchunk = total_f4 / CHUNK_F4;

    Acc ac = {0.f,0.f,0.f,0.f, 0.f,0.f,0.f,0.f, 0.f,0.f,0.f,0.f};

    for (int c = blockIdx.x; c < nchunk; c += grid) {
        if (tid == 0) {
            const int pc = c + PF_D * grid;
            if (pc < nchunk) {
                prefetch_l2(pred + (size_t)pc * CHUNK_F4, CHUNK_F4 * 16);
                prefetch_l2(targ + (size_t)pc * CHUNK_F4, CHUNK_F4 * 16);
            }
        }
        const size_t base = (size_t)c * CHUNK_F4;
        // CHUNK_F4 (512) and NTHR (256) are multiples of 128, so the column
        // group of both reads is tid & 127 — accumulator mapping is stable.
        const float4 x0 = __ldcs(pred + base + tid);
        const float4 t0 = __ldcs(targ + base + tid);
        const float4 x1 = __ldcs(pred + base + tid + NTHR);
        const float4 t1 = __ldcs(targ + base + tid + NTHR);
        bl_acc(ac, x0, t0);
        bl_acc(ac, x1, t1);
    }
    // tail f4 groups (total_f4 % CHUNK_F4 != 0): block 0, column-preserving
    if (blockIdx.x == 0) {
        for (int i = nchunk * CHUNK_F4 + tid; i < total_f4; i += NTHR) {
            const float4 x = __ldg(pred + i);
            const float4 t = __ldg(targ + i);
            bl_acc(ac, x, t);
        }
    }

    // ---- intra-block reduction over the 2 row-lanes ----
    __shared__ float4 sbuf[NTHR];
    const int rlane = tid >> 7;   // 0..1

    sbuf[tid] = make_float4(ac.a0, ac.a1, ac.a2, ac.a3);
    __syncthreads();
    if (rlane == 0) {
        float4 u = sbuf[tid + 128];
        ac.a0 += u.x; ac.a1 += u.y; ac.a2 += u.z; ac.a3 += u.w;
    }
    __syncthreads();
    sbuf[tid] = make_float4(ac.b0, ac.b1, ac.b2, ac.b3);
    __syncthreads();
    if (rlane == 0) {
        float4 u = sbuf[tid + 128];
        ac.b0 += u.x; ac.b1 += u.y; ac.b2 += u.z; ac.b3 += u.w;
    }
    __syncthreads();
    sbuf[tid] = make_float4(ac.p0, ac.p1, ac.p2, ac.p3);
    __syncthreads();
    if (rlane == 0) {
        float4 u = sbuf[tid + 128];
        ac.p0 += u.x; ac.p1 += u.y; ac.p2 += u.z; ac.p3 += u.w;

        const int rep = blockIdx.x & (REPL - 1);
        const int c = (tid & (C4 - 1)) * 4;
        atomicAdd(&g_accA[rep][c+0], ac.a0); atomicAdd(&g_accA[rep][c+1], ac.a1);
        atomicAdd(&g_accA[rep][c+2], ac.a2); atomicAdd(&g_accA[rep][c+3], ac.a3);
        atomicAdd(&g_accB[rep][c+0], ac.b0); atomicAdd(&g_accB[rep][c+1], ac.b1);
        atomicAdd(&g_accB[rep][c+2], ac.b2); atomicAdd(&g_accB[rep][c+3], ac.b3);
        atomicAdd(&g_accP[rep][c+0], ac.p0); atomicAdd(&g_accP[rep][c+1], ac.p1);
        atomicAdd(&g_accP[rep][c+2], ac.p2); atomicAdd(&g_accP[rep][c+3], ac.p3);
    }

    // ---- last-block finalize ----
    __shared__ bool s_last;
    __threadfence();
    __syncthreads();
    if (tid == 0) {
        unsigned int prev = atomicAdd(&g_done, 1u);
        s_last = (prev == gridDim.x - 1);
    }
    __syncthreads();
    if (!s_last) return;

    __threadfence();
    {
        const float Bf = (float)Bn;
        float contrib = 0.0f;

        #pragma unroll
        for (int k = 0; k < 2; k++) {
            const int c = tid + k * NTHR;     // covers 512 columns
            float A = 0.f, Bv = 0.f, P = 0.f;
            #pragma unroll
            for (int r = 0; r < REPL; r++) {
                A += g_accA[r][c]; Bv += g_accB[r][c]; P += g_accP[r][c];
                g_accA[r][c] = 0.0f; g_accB[r][c] = 0.0f; g_accP[r][c] = 0.0f;
            }
            const float bn = pos_prop[c] * Bf;
            const bool  majIs1 = (P >= bn);
            const float n_maj  = majIs1 ? P : (Bf - P);
            const float n_min  = Bf - n_maj;
            const float w_maj  = bn / n_maj;
            const float w_min  = (n_min > 0.0f) ? (Bf - bn) / fmaxf(n_min, 1.0f)
                                                : 1.0f;
            const float w1 = majIs1 ? w_maj : w_min;
            const float w0 = majIs1 ? w_min : w_maj;
            contrib += w0 * A + w1 * Bv;
        }
        if (tid == 0) g_done = 0u;

        __shared__ float sh[NTHR];
        sh[tid] = contrib;
        __syncthreads();
        #pragma unroll
        for (int s = NTHR / 2; s > 0; s >>= 1) {
            if (tid < s) sh[tid] += sh[tid + s];
            __syncthreads();
        }
        if (tid == 0) out[0] = sh[0] / (Bf * (float)CCOLS);
    }
}

extern "C" void kernel_launch(void* const* d_in, const int* in_sizes, int n_in,
                              void* d_out, int out_size) {
    const float* pred = (const float*)d_in[0];
    const float* targ = (const float*)d_in[1];
    const float* pp   = (const float*)d_in[2];
    const int Cc = in_sizes[2];          // 512
    const int Bn = in_sizes[0] / Cc;     // 65536

    bl_pf_kernel<<<NBLK, NTHR>>>((const float4*)pred, (const float4*)targ,
                                 pp, (float*)d_out, Bn);
}

// round 15
// speedup vs baseline: 1.0507x; 1.0507x over previous
#include <cuda_runtime.h>
#include <cstdint>

// BalancedLoss fused kernel, R15 == R10 exactly (control re-bench).
// Grid-stride 8KB chunks -> collectively-sequential DRAM sweep;
// cp.async.bulk.prefetch.L2 PF_D=2 grid-strides ahead; 256 thr x 5 CTA/SM.
// Per column c: A_c = sum (1-t)*softplus(x), B_c = sum t*(softplus(x)-x),
// P_c = sum t;  loss = sum_c (w0_c*A_c + w1_c*B_c) / (B*C).

#define CCOLS 512
#define C4    128        // float4 groups per row
#define NBLK  740        // 5 CTAs/SM
#define NTHR  256
#define CHUNK_F4 512     // float4 per tensor per chunk (8 KB)
#define PF_D  2          // prefetch distance in grid-strides
#define REPL  4          // accumulator replicas (atomic contention)

__device__ float g_accA[REPL][CCOLS];
__device__ float g_accB[REPL][CCOLS];
__device__ float g_accP[REPL][CCOLS];
__device__ unsigned int g_done;

__device__ __forceinline__ void prefetch_l2(const void* p, uint32_t bytes) {
    asm volatile("cp.async.bulk.prefetch.L2.global [%0], %1;"
                 :: "l"(p), "r"(bytes) : "memory");
}

__device__ __forceinline__ float softplus_f(float x) {
    return fmaxf(x, 0.0f) + __logf(1.0f + __expf(-fabsf(x)));
}

struct Acc {
    float a0, a1, a2, a3, b0, b1, b2, b3, p0, p1, p2, p3;
};

__device__ __forceinline__ void bl_acc(Acc& ac, const float4& x, const float4& t) {
    float s;
    s = softplus_f(x.x); ac.a0 += s - s*t.x; ac.b0 += (s - x.x)*t.x; ac.p0 += t.x;
    s = softplus_f(x.y); ac.a1 += s - s*t.y; ac.b1 += (s - x.y)*t.y; ac.p1 += t.y;
    s = softplus_f(x.z); ac.a2 += s - s*t.z; ac.b2 += (s - x.z)*t.z; ac.p2 += t.z;
    s = softplus_f(x.w); ac.a3 += s - s*t.w; ac.b3 += (s - x.w)*t.w; ac.p3 += t.w;
}

__global__ __launch_bounds__(NTHR, 5)
void bl_pf_kernel(const float4* __restrict__ pred,
                  const float4* __restrict__ targ,
                  const float* __restrict__ pos_prop,
                  float* __restrict__ out,
                  int Bn) {
    const int tid  = threadIdx.x;
    const int grid = gridDim.x;
    const int total_f4 = Bn * C4;
    const int nchunk = total_f4 / CHUNK_F4;

    Acc ac = {0.f,0.f,0.f,0.f, 0.f,0.f,0.f,0.f, 0.f,0.f,0.f,0.f};

    for (int c = blockIdx.x; c < nchunk; c += grid) {
        if (tid == 0) {
            const int pc = c + PF_D * grid;
            if (pc < nchunk) {
                prefetch_l2(pred + (size_t)pc * CHUNK_F4, CHUNK_F4 * 16);
                prefetch_l2(targ + (size_t)pc * CHUNK_F4, CHUNK_F4 * 16);
            }
        }
        const size_t base = (size_t)c * CHUNK_F4;
        // CHUNK_F4 (512) and NTHR (256) are multiples of 128, so the column
        // group of both reads is tid & 127 — accumulator mapping is stable.
        const float4 x0 = __ldcs(pred + base + tid);
        const float4 t0 = __ldcs(targ + base + tid);
        const float4 x1 = __ldcs(pred + base + tid + NTHR);
        const float4 t1 = __ldcs(targ + base + tid + NTHR);
        bl_acc(ac, x0, t0);
        bl_acc(ac, x1, t1);
    }
    // tail f4 groups (total_f4 % CHUNK_F4 != 0): block 0, column-preserving
    if (blockIdx.x == 0) {
        for (int i = nchunk * CHUNK_F4 + tid; i < total_f4; i += NTHR) {
            const float4 x = __ldg(pred + i);
            const float4 t = __ldg(targ + i);
            bl_acc(ac, x, t);
        }
    }

    // ---- intra-block reduction over the 2 row-lanes ----
    __shared__ float4 sbuf[NTHR];
    const int rlane = tid >> 7;   // 0..1

    sbuf[tid] = make_float4(ac.a0, ac.a1, ac.a2, ac.a3);
    __syncthreads();
    if (rlane == 0) {
        float4 u = sbuf[tid + 128];
        ac.a0 += u.x; ac.a1 += u.y; ac.a2 += u.z; ac.a3 += u.w;
    }
    __syncthreads();
    sbuf[tid] = make_float4(ac.b0, ac.b1, ac.b2, ac.b3);
    __syncthreads();
    if (rlane == 0) {
        float4 u = sbuf[tid + 128];
        ac.b0 += u.x; ac.b1 += u.y; ac.b2 += u.z; ac.b3 += u.w;
    }
    __syncthreads();
    sbuf[tid] = make_float4(ac.p0, ac.p1, ac.p2, ac.p3);
    __syncthreads();
    if (rlane == 0) {
        float4 u = sbuf[tid + 128];
        ac.p0 += u.x; ac.p1 += u.y; ac.p2 += u.z; ac.p3 += u.w;

        const int rep = blockIdx.x & (REPL - 1);
        const int c = (tid & (C4 - 1)) * 4;
        atomicAdd(&g_accA[rep][c+0], ac.a0); atomicAdd(&g_accA[rep][c+1], ac.a1);
        atomicAdd(&g_accA[rep][c+2], ac.a2); atomicAdd(&g_accA[rep][c+3], ac.a3);
        atomicAdd(&g_accB[rep][c+0], ac.b0); atomicAdd(&g_accB[rep][c+1], ac.b1);
        atomicAdd(&g_accB[rep][c+2], ac.b2); atomicAdd(&g_accB[rep][c+3], ac.b3);
        atomicAdd(&g_accP[rep][c+0], ac.p0); atomicAdd(&g_accP[rep][c+1], ac.p1);
        atomicAdd(&g_accP[rep][c+2], ac.p2); atomicAdd(&g_accP[rep][c+3], ac.p3);
    }

    // ---- last-block finalize ----
    __shared__ bool s_last;
    __threadfence();
    __syncthreads();
    if (tid == 0) {
        unsigned int prev = atomicAdd(&g_done, 1u);
        s_last = (prev == gridDim.x - 1);
    }
    __syncthreads();
    if (!s_last) return;

    __threadfence();
    {
        const float Bf = (float)Bn;
        float contrib = 0.0f;

        #pragma unroll
        for (int k = 0; k < 2; k++) {
            const int c = tid + k * NTHR;     // covers 512 columns
            float A = 0.f, Bv = 0.f, P = 0.f;
            #pragma unroll
            for (int r = 0; r < REPL; r++) {
                A += g_accA[r][c]; Bv += g_accB[r][c]; P += g_accP[r][c];
                g_accA[r][c] = 0.0f; g_accB[r][c] = 0.0f; g_accP[r][c] = 0.0f;
            }
            const float bn = pos_prop[c] * Bf;
            const bool  majIs1 = (P >= bn);
            const float n_maj  = majIs1 ? P : (Bf - P);
            const float n_min  = Bf - n_maj;
            const float w_maj  = bn / n_maj;
            const float w_min  = (n_min > 0.0f) ? (Bf - bn) / fmaxf(n_min, 1.0f)
                                                : 1.0f;
            const float w1 = majIs1 ? w_maj : w_min;
            const float w0 = majIs1 ? w_min : w_maj;
            contrib += w0 * A + w1 * Bv;
        }
        if (tid == 0) g_done = 0u;

        __shared__ float sh[NTHR];
        sh[tid] = contrib;
        __syncthreads();
        #pragma unroll
        for (int s = NTHR / 2; s > 0; s >>= 1) {
            if (tid < s) sh[tid] += sh[tid + s];
            __syncthreads();
        }
        if (tid == 0) out[0] = sh[0] / (Bf * (float)CCOLS);
    }
}

extern "C" void kernel_launch(void* const* d_in, const int* in_sizes, int n_in,
                              void* d_out, int out_size) {
    const float* pred = (const float*)d_in[0];
    const float* targ = (const float*)d_in[1];
    const float* pp   = (const float*)d_in[2];
    const int Cc = in_sizes[2];          // 512
    const int Bn = in_sizes[0] / Cc;     // 65536

    bl_pf_kernel<<<NBLK, NTHR>>>((const float4*)pred, (const float4*)targ,
                                 pp, (float*)d_out, Bn);
}

// round 16
// speedup vs baseline: 1.0963x; 1.0434x over previous
#include <cuda_runtime.h>
#include <cstdint>

// BalancedLoss fused kernel, R16: R10 structure (grid-stride 8KB chunks =>
// collectively-sequential DRAM sweep, L2 prefetch PF_D=2), single change:
// __launch_bounds__(256, 6) -> 48 warps/SM (regs forced <= 42).
// Per column c: A_c = sum (1-t)*softplus(x), B_c = sum t*(softplus(x)-x),
// P_c = sum t;  loss = sum_c (w0_c*A_c + w1_c*B_c) / (B*C).

#define CCOLS 512
#define C4    128        // float4 groups per row
#define NBLK  888        // 6 CTAs/SM on 148 SMs
#define NTHR  256
#define CHUNK_F4 512     // float4 per tensor per chunk (8 KB)
#define PF_D  2          // prefetch distance in grid-strides
#define REPL  4          // accumulator replicas (atomic contention)

__device__ float g_accA[REPL][CCOLS];
__device__ float g_accB[REPL][CCOLS];
__device__ float g_accP[REPL][CCOLS];
__device__ unsigned int g_done;

__device__ __forceinline__ void prefetch_l2(const void* p, uint32_t bytes) {
    asm volatile("cp.async.bulk.prefetch.L2.global [%0], %1;"
                 :: "l"(p), "r"(bytes) : "memory");
}

__device__ __forceinline__ float softplus_f(float x) {
    return fmaxf(x, 0.0f) + __logf(1.0f + __expf(-fabsf(x)));
}

struct Acc {
    float a0, a1, a2, a3, b0, b1, b2, b3, p0, p1, p2, p3;
};

__device__ __forceinline__ void bl_acc(Acc& ac, const float4& x, const float4& t) {
    float s;
    s = softplus_f(x.x); ac.a0 += s - s*t.x; ac.b0 += (s - x.x)*t.x; ac.p0 += t.x;
    s = softplus_f(x.y); ac.a1 += s - s*t.y; ac.b1 += (s - x.y)*t.y; ac.p1 += t.y;
    s = softplus_f(x.z); ac.a2 += s - s*t.z; ac.b2 += (s - x.z)*t.z; ac.p2 += t.z;
    s = softplus_f(x.w); ac.a3 += s - s*t.w; ac.b3 += (s - x.w)*t.w; ac.p3 += t.w;
}

__global__ __launch_bounds__(NTHR, 6)
void bl_pf_kernel(const float4* __restrict__ pred,
                  const float4* __restrict__ targ,
                  const float* __restrict__ pos_prop,
                  float* __restrict__ out,
                  int Bn) {
    const int tid  = threadIdx.x;
    const int grid = gridDim.x;
    const int total_f4 = Bn * C4;
    const int nchunk = total_f4 / CHUNK_F4;

    Acc ac = {0.f,0.f,0.f,0.f, 0.f,0.f,0.f,0.f, 0.f,0.f,0.f,0.f};

    for (int c = blockIdx.x; c < nchunk; c += grid) {
        if (tid == 0) {
            const int pc = c + PF_D * grid;
            if (pc < nchunk) {
                prefetch_l2(pred + (size_t)pc * CHUNK_F4, CHUNK_F4 * 16);
                prefetch_l2(targ + (size_t)pc * CHUNK_F4, CHUNK_F4 * 16);
            }
        }
        const size_t base = (size_t)c * CHUNK_F4;
        // CHUNK_F4 (512) and NTHR (256) are multiples of 128, so the column
        // group of both reads is tid & 127 — accumulator mapping is stable.
        const float4 x0 = __ldcs(pred + base + tid);
        const float4 t0 = __ldcs(targ + base + tid);
        const float4 x1 = __ldcs(pred + base + tid + NTHR);
        const float4 t1 = __ldcs(targ + base + tid + NTHR);
        bl_acc(ac, x0, t0);
        bl_acc(ac, x1, t1);
    }
    // tail f4 groups (total_f4 % CHUNK_F4 != 0): block 0, column-preserving
    if (blockIdx.x == 0) {
        for (int i = nchunk * CHUNK_F4 + tid; i < total_f4; i += NTHR) {
            const float4 x = __ldg(pred + i);
            const float4 t = __ldg(targ + i);
            bl_acc(ac, x, t);
        }
    }

    // ---- intra-block reduction over the 2 row-lanes ----
    __shared__ float4 sbuf[NTHR];
    const int rlane = tid >> 7;   // 0..1

    sbuf[tid] = make_float4(ac.a0, ac.a1, ac.a2, ac.a3);
    __syncthreads();
    if (rlane == 0) {
        float4 u = sbuf[tid + 128];
        ac.a0 += u.x; ac.a1 += u.y; ac.a2 += u.z; ac.a3 += u.w;
    }
    __syncthreads();
    sbuf[tid] = make_float4(ac.b0, ac.b1, ac.b2, ac.b3);
    __syncthreads();
    if (rlane == 0) {
        float4 u = sbuf[tid + 128];
        ac.b0 += u.x; ac.b1 += u.y; ac.b2 += u.z; ac.b3 += u.w;
    }
    __syncthreads();
    sbuf[tid] = make_float4(ac.p0, ac.p1, ac.p2, ac.p3);
    __syncthreads();
    if (rlane == 0) {
        float4 u = sbuf[tid + 128];
        ac.p0 += u.x; ac.p1 += u.y; ac.p2 += u.z; ac.p3 += u.w;

        const int rep = blockIdx.x & (REPL - 1);
        const int c = (tid & (C4 - 1)) * 4;
        atomicAdd(&g_accA[rep][c+0], ac.a0); atomicAdd(&g_accA[rep][c+1], ac.a1);
        atomicAdd(&g_accA[rep][c+2], ac.a2); atomicAdd(&g_accA[rep][c+3], ac.a3);
        atomicAdd(&g_accB[rep][c+0], ac.b0); atomicAdd(&g_accB[rep][c+1], ac.b1);
        atomicAdd(&g_accB[rep][c+2], ac.b2); atomicAdd(&g_accB[rep][c+3], ac.b3);
        atomicAdd(&g_accP[rep][c+0], ac.p0); atomicAdd(&g_accP[rep][c+1], ac.p1);
        atomicAdd(&g_accP[rep][c+2], ac.p2); atomicAdd(&g_accP[rep][c+3], ac.p3);
    }

    // ---- last-block finalize ----
    __shared__ bool s_last;
    __threadfence();
    __syncthreads();
    if (tid == 0) {
        unsigned int prev = atomicAdd(&g_done, 1u);
        s_last = (prev == gridDim.x - 1);
    }
    __syncthreads();
    if (!s_last) return;

    __threadfence();
    {
        const float Bf = (float)Bn;
        float contrib = 0.0f;

        #pragma unroll
        for (int k = 0; k < 2; k++) {
            const int c = tid + k * NTHR;     // covers 512 columns
            float A = 0.f, Bv = 0.f, P = 0.f;
            #pragma unroll
            for (int r = 0; r < REPL; r++) {
                A += g_accA[r][c]; Bv += g_accB[r][c]; P += g_accP[r][c];
                g_accA[r][c] = 0.0f; g_accB[r][c] = 0.0f; g_accP[r][c] = 0.0f;
            }
            const float bn = pos_prop[c] * Bf;
            const bool  majIs1 = (P >= bn);
            const float n_maj  = majIs1 ? P : (Bf - P);
            const float n_min  = Bf - n_maj;
            const float w_maj  = bn / n_maj;
            const float w_min  = (n_min > 0.0f) ? (Bf - bn) / fmaxf(n_min, 1.0f)
                                                : 1.0f;
            const float w1 = majIs1 ? w_maj : w_min;
            const float w0 = majIs1 ? w_min : w_maj;
            contrib += w0 * A + w1 * Bv;
        }
        if (tid == 0) g_done = 0u;

        __shared__ float sh[NTHR];
        sh[tid] = contrib;
        __syncthreads();
        #pragma unroll
        for (int s = NTHR / 2; s > 0; s >>= 1) {
            if (tid < s) sh[tid] += sh[tid + s];
            __syncthreads();
        }
        if (tid == 0) out[0] = sh[0] / (Bf * (float)CCOLS);
    }
}

extern "C" void kernel_launch(void* const* d_in, const int* in_sizes, int n_in,
                              void* d_out, int out_size) {
    const float* pred = (const float*)d_in[0];
    const float* targ = (const float*)d_in[1];
    const float* pp   = (const float*)d_in[2];
    const int Cc = in_sizes[2];          // 512
    const int Bn = in_sizes[0] / Cc;     // 65536

    bl_pf_kernel<<<NBLK, NTHR>>>((const float4*)pred, (const float4*)targ,
                                 pp, (float*)d_out, Bn);
}